// round 2
// baseline (speedup 1.0000x reference)
#include <cuda_runtime.h>
#include <math.h>

// Problem constants
static constexpr int B = 64;
static constexpr int T = 512;
static constexpr int I = 1024;
static constexpr int H = 1024;
static constexpr int G4H = 4 * H;   // 4096

// Scratch in device globals (no allocation allowed)
__device__ float g_xproj[(size_t)T * B * G4H];  // [T][B][4H]  (512 MB)
__device__ float g_h[2][B * H];                 // h ping-pong
__device__ float g_c[B * H];                    // cell state

// ---------------------------------------------------------------------------
// init: zero h[0] and c
// ---------------------------------------------------------------------------
__global__ void init_kernel() {
    int i = blockIdx.x * blockDim.x + threadIdx.x;
    if (i < B * H) {
        g_h[0][i] = 0.0f;
        g_c[i] = 0.0f;
    }
}

// ---------------------------------------------------------------------------
// xproj GEMM: C[m, n] = sum_k x[m,k] * Wx[k,n] + b[n]
//   x: [B*T, I] row-major (m = b*T + t)
//   Wx column block n0..n0+127 lies entirely inside one gate's [I,H] matrix
//   output stored as g_xproj[(t*B + b)*4096 + n]
// 128x128 tile, BK=16, 256 threads, 8x8 register tile
// ---------------------------------------------------------------------------
static constexpr int BM = 128;
static constexpr int BN = 128;
static constexpr int BK = 16;

__global__ void __launch_bounds__(256) xproj_kernel(
    const float* __restrict__ x,
    const float* __restrict__ w0, const float* __restrict__ w1,
    const float* __restrict__ w2, const float* __restrict__ w3,
    const float* __restrict__ b0, const float* __restrict__ b1,
    const float* __restrict__ b2, const float* __restrict__ b3)
{
    const int tid = threadIdx.x;
    const int mb = blockIdx.y;
    const int nb = blockIdx.x;
    const int m0 = mb * BM;
    const int n0 = nb * BN;              // multiple of 128, < 4096
    const int gate = n0 >> 10;           // which weight matrix
    const float* __restrict__ w = (gate == 0) ? w0 : (gate == 1) ? w1 : (gate == 2) ? w2 : w3;
    const float* __restrict__ bias = (gate == 0) ? b0 : (gate == 1) ? b1 : (gate == 2) ? b2 : b3;
    const int j0 = n0 & (H - 1);

    __shared__ float As[BK][BM + 4];     // [k][m], stride 132
    __shared__ float Bs[BK][BN + 4];     // [k][n], stride 132

    const int tx = tid & 15;             // col group (8 cols)
    const int ty = tid >> 4;             // row group (8 rows)

    float acc[8][8];
    #pragma unroll
    for (int i = 0; i < 8; ++i)
        #pragma unroll
        for (int j = 0; j < 8; ++j) acc[i][j] = 0.0f;

    // A load mapping: 128 rows x 16 k = 512 float4; 2 per thread
    const int ar = tid >> 2;             // 0..63 (then +64)
    const int ak = (tid & 3) * 4;        // k quad
    // B load mapping: 16 k x 128 cols = 512 float4; 2 per thread
    const int bk = tid >> 5;             // 0..7 (then +8)
    const int bc = (tid & 31) * 4;       // col quad

    for (int k0 = 0; k0 < I; k0 += BK) {
        #pragma unroll
        for (int p = 0; p < 2; ++p) {
            int r = ar + p * 64;
            float4 v = *reinterpret_cast<const float4*>(&x[(size_t)(m0 + r) * I + k0 + ak]);
            As[ak + 0][r] = v.x;
            As[ak + 1][r] = v.y;
            As[ak + 2][r] = v.z;
            As[ak + 3][r] = v.w;
        }
        #pragma unroll
        for (int p = 0; p < 2; ++p) {
            int kk = bk + p * 8;
            float4 v = *reinterpret_cast<const float4*>(&w[(size_t)(k0 + kk) * H + j0 + bc]);
            *reinterpret_cast<float4*>(&Bs[kk][bc]) = v;
        }
        __syncthreads();

        #pragma unroll
        for (int kk = 0; kk < BK; ++kk) {
            float4 a0 = *reinterpret_cast<const float4*>(&As[kk][ty * 8]);
            float4 a1 = *reinterpret_cast<const float4*>(&As[kk][ty * 8 + 4]);
            float4 c0 = *reinterpret_cast<const float4*>(&Bs[kk][tx * 8]);
            float4 c1 = *reinterpret_cast<const float4*>(&Bs[kk][tx * 8 + 4]);
            float a[8] = {a0.x, a0.y, a0.z, a0.w, a1.x, a1.y, a1.z, a1.w};
            float bb[8] = {c0.x, c0.y, c0.z, c0.w, c1.x, c1.y, c1.z, c1.w};
            #pragma unroll
            for (int i = 0; i < 8; ++i)
                #pragma unroll
                for (int j = 0; j < 8; ++j)
                    acc[i][j] += a[i] * bb[j];
        }
        __syncthreads();
    }

    // epilogue: add bias, scatter to [t][b][4H]
    #pragma unroll
    for (int i = 0; i < 8; ++i) {
        int m = m0 + ty * 8 + i;
        int t = m & (T - 1);
        int bi_ = m >> 9;                // m / T
        size_t base = ((size_t)t * B + bi_) * G4H + n0;
        #pragma unroll
        for (int j = 0; j < 8; ++j) {
            int n = tx * 8 + j;
            g_xproj[base + n] = acc[i][j] + bias[j0 + n];
        }
    }
}

// ---------------------------------------------------------------------------
// Fused LSTM step: gates = xproj[t] + h_t @ Wh ; activations ; c,h update
// Grid: 128 CTAs. CTA cg owns H-columns [cg*8, cg*8+8) for ALL 4 gates and
// all 64 batch rows -> fully local pointwise update, no cross-CTA races.
// GEMM tile per CTA: 64 rows x 32 fused cols (fc = gate*8 + jj), K=1024.
// 256 threads: tx = tid&15 -> 2 fused cols, ty = tid>>4 -> 4 rows.
// ---------------------------------------------------------------------------
static constexpr int KC = 32;            // K chunk
static constexpr int HS_STRIDE = 68;     // hs row-dim stride (64 + pad)
static constexpr int WS_STRIDE = 36;     // ws col-dim stride (32 + pad)

__global__ void __launch_bounds__(256) lstm_step_kernel(
    int t,
    const float* __restrict__ wh0, const float* __restrict__ wh1,
    const float* __restrict__ wh2, const float* __restrict__ wh3,
    float* __restrict__ out)
{
    const int tid = threadIdx.x;
    const int cg = blockIdx.x;           // 0..127
    const int j0 = cg * 8;

    const float* __restrict__ hin = g_h[t & 1];
    float* __restrict__ hout = g_h[(t + 1) & 1];

    __shared__ float hs[KC * HS_STRIDE];     // [k][row]
    __shared__ float ws[KC * WS_STRIDE];     // [k][fc]
    __shared__ float gt[64 * WS_STRIDE];     // [row][fc]

    const int tx = tid & 15;
    const int ty = tid >> 4;

    float acc[4][2];
    #pragma unroll
    for (int r = 0; r < 4; ++r) { acc[r][0] = 0.0f; acc[r][1] = 0.0f; }

    // load mappings
    const int hr = tid >> 3;             // h row 0..31 (then +32)
    const int hkq = (tid & 7) * 4;       // k quad within chunk
    const int wkk = tid >> 3;            // ws k row 0..31
    const int wf4 = tid & 7;             // fused-col quad 0..7
    const int wgate = wf4 >> 1;
    const int wjj = (wf4 & 1) * 4;
    const float* __restrict__ wsel = (wgate == 0) ? wh0 : (wgate == 1) ? wh1
                                   : (wgate == 2) ? wh2 : wh3;

    for (int k0 = 0; k0 < H; k0 += KC) {
        // h tile: [KC k][64 rows], transposed store
        #pragma unroll
        for (int p = 0; p < 2; ++p) {
            int r = hr + p * 32;
            float4 v = *reinterpret_cast<const float4*>(&hin[r * H + k0 + hkq]);
            hs[(hkq + 0) * HS_STRIDE + r] = v.x;
            hs[(hkq + 1) * HS_STRIDE + r] = v.y;
            hs[(hkq + 2) * HS_STRIDE + r] = v.z;
            hs[(hkq + 3) * HS_STRIDE + r] = v.w;
        }
        // Wh tile: [KC k][32 fused cols]
        {
            float4 v = *reinterpret_cast<const float4*>(&wsel[(size_t)(k0 + wkk) * H + j0 + wjj]);
            *reinterpret_cast<float4*>(&ws[wkk * WS_STRIDE + wf4 * 4]) = v;
        }
        __syncthreads();

        #pragma unroll
        for (int kk = 0; kk < KC; ++kk) {
            float4 a = *reinterpret_cast<const float4*>(&hs[kk * HS_STRIDE + ty * 4]);
            float2 bb = *reinterpret_cast<const float2*>(&ws[kk * WS_STRIDE + tx * 2]);
            acc[0][0] += a.x * bb.x;  acc[0][1] += a.x * bb.y;
            acc[1][0] += a.y * bb.x;  acc[1][1] += a.y * bb.y;
            acc[2][0] += a.z * bb.x;  acc[2][1] += a.z * bb.y;
            acc[3][0] += a.w * bb.x;  acc[3][1] += a.w * bb.y;
        }
        __syncthreads();
    }

    // add xproj, stash gates in smem for the cross-gate pointwise
    #pragma unroll
    for (int r = 0; r < 4; ++r) {
        int row = ty * 4 + r;
        size_t xb = ((size_t)t * B + row) * G4H;
        #pragma unroll
        for (int c = 0; c < 2; ++c) {
            int fc = tx * 2 + c;
            int gate = fc >> 3;
            int jj = fc & 7;
            float v = acc[r][c] + g_xproj[xb + (size_t)gate * H + j0 + jj];
            gt[row * WS_STRIDE + fc] = v;
        }
    }
    __syncthreads();

    // pointwise LSTM cell: 512 (row, j) elements, 2 per thread
    #pragma unroll
    for (int e0 = 0; e0 < 2; ++e0) {
        int e = tid * 2 + e0;
        int row = e >> 3;
        int jj = e & 7;
        float gi = gt[row * WS_STRIDE + 0 * 8 + jj];
        float gf = gt[row * WS_STRIDE + 1 * 8 + jj];
        float gg = gt[row * WS_STRIDE + 2 * 8 + jj];
        float go = gt[row * WS_STRIDE + 3 * 8 + jj];
        float ig = 1.0f / (1.0f + expf(-gi));
        float fg = 1.0f / (1.0f + expf(-gf));
        float gv = tanhf(gg);
        float og = 1.0f / (1.0f + expf(-go));
        int j = j0 + jj;
        float c = fg * g_c[row * H + j] + ig * gv;
        g_c[row * H + j] = c;
        float h = og * tanhf(c);
        hout[row * H + j] = h;
        // hseq: [B][T][H]
        out[((size_t)row * T + t) * H + j] = h;
        if (t == T - 1) {
            size_t off = (size_t)B * T * H;
            out[off + (size_t)row * H + j] = h;            // ht
            out[off + (size_t)B * H + (size_t)row * H + j] = c;  // ct
        }
    }
}

// ---------------------------------------------------------------------------
extern "C" void kernel_launch(void* const* d_in, const int* in_sizes, int n_in,
                              void* d_out, int out_size)
{
    const float* x   = (const float*)d_in[0];
    const float* wii = (const float*)d_in[1];
    const float* whi = (const float*)d_in[2];
    const float* bi  = (const float*)d_in[3];
    const float* wif = (const float*)d_in[4];
    const float* whf = (const float*)d_in[5];
    const float* bf  = (const float*)d_in[6];
    const float* wig = (const float*)d_in[7];
    const float* whg = (const float*)d_in[8];
    const float* bg  = (const float*)d_in[9];
    const float* wio = (const float*)d_in[10];
    const float* who = (const float*)d_in[11];
    const float* bo  = (const float*)d_in[12];
    float* out = (float*)d_out;

    init_kernel<<<(B * H + 255) / 256, 256>>>();

    dim3 gx(G4H / BN, (B * T) / BM);   // (32, 256)
    xproj_kernel<<<gx, 256>>>(x, wii, wif, wig, wio, bi, bf, bg, bo);

    for (int t = 0; t < T; ++t)
        lstm_step_kernel<<<128, 256>>>(t, whi, whf, whg, who, out);
}

// round 3
// speedup vs baseline: 1.0699x; 1.0699x over previous
#include <cuda_runtime.h>
#include <math.h>

typedef unsigned long long ull;

// Problem constants
static constexpr int B = 64;
static constexpr int T = 512;
static constexpr int I = 1024;
static constexpr int H = 1024;
static constexpr int G4H = 4 * H;   // 4096

// Scratch in device globals (no allocation allowed)
__device__ float g_xproj[(size_t)T * B * G4H];  // [T][B][4H]
__device__ float g_h[2][B * H];                 // h ping-pong
__device__ float g_c[B * H];                    // cell state

// ---------------------------------------------------------------------------
// f32x2 packed-FMA helpers (Blackwell: fma.rn.f32x2, PTX 8.6+/sm_100+)
// ---------------------------------------------------------------------------
__device__ __forceinline__ ull dup2(float x) {
    ull r; asm("mov.b64 %0, {%1, %1};" : "=l"(r) : "f"(x)); return r;
}
__device__ __forceinline__ void fma2(ull& d, ull a, ull b) {
    asm("fma.rn.f32x2 %0, %1, %2, %0;" : "+l"(d) : "l"(a), "l"(b));
}
__device__ __forceinline__ float2 unpack2(ull v) {
    float2 f; asm("mov.b64 {%0, %1}, %2;" : "=f"(f.x), "=f"(f.y) : "l"(v)); return f;
}
__device__ __forceinline__ ull d2l(double d) { return __double_as_longlong(d); }

__device__ __forceinline__ float fast_tanh(float x) {
    float y; asm("tanh.approx.f32 %0, %1;" : "=f"(y) : "f"(x)); return y;
}
__device__ __forceinline__ float fast_sigmoid(float x) {
    return 0.5f * fast_tanh(0.5f * x) + 0.5f;
}

// ---------------------------------------------------------------------------
// init: zero h[0] and c
// ---------------------------------------------------------------------------
__global__ void init_kernel() {
    int i = blockIdx.x * blockDim.x + threadIdx.x;
    if (i < B * H) {
        g_h[0][i] = 0.0f;
        g_c[i] = 0.0f;
    }
}

// ---------------------------------------------------------------------------
// xproj GEMM: C[m, n] = sum_k x[m,k] * Wx[k,n] + b[n]
// 128x128 tile, BK=16, 256 threads, 8x8 register tile done as 4x8 FFMA2
// ---------------------------------------------------------------------------
static constexpr int BM = 128;
static constexpr int BN = 128;
static constexpr int BK = 16;

__global__ void __launch_bounds__(256) xproj_kernel(
    const float* __restrict__ x,
    const float* __restrict__ w0, const float* __restrict__ w1,
    const float* __restrict__ w2, const float* __restrict__ w3,
    const float* __restrict__ b0, const float* __restrict__ b1,
    const float* __restrict__ b2, const float* __restrict__ b3)
{
    const int tid = threadIdx.x;
    const int mb = blockIdx.y;
    const int nb = blockIdx.x;
    const int m0 = mb * BM;
    const int n0 = nb * BN;              // multiple of 128, < 4096
    const int gate = n0 >> 10;
    const float* __restrict__ w = (gate == 0) ? w0 : (gate == 1) ? w1 : (gate == 2) ? w2 : w3;
    const float* __restrict__ bias = (gate == 0) ? b0 : (gate == 1) ? b1 : (gate == 2) ? b2 : b3;
    const int j0 = n0 & (H - 1);

    __shared__ float As[BK][BM + 4];     // [k][m]
    __shared__ float Bs[BK][BN + 4];     // [k][n]

    const int tx = tid & 15;             // col group (8 cols)
    const int ty = tid >> 4;             // row group (8 rows)

    ull acc[4][8];                       // row-pairs (f32x2) x 8 cols
    #pragma unroll
    for (int i = 0; i < 4; ++i)
        #pragma unroll
        for (int j = 0; j < 8; ++j) acc[i][j] = 0ULL;

    const int ar = tid >> 2;             // 0..63 (then +64)
    const int ak = (tid & 3) * 4;
    const int bk = tid >> 5;             // 0..7 (then +8)
    const int bc = (tid & 31) * 4;

    for (int k0 = 0; k0 < I; k0 += BK) {
        #pragma unroll
        for (int p = 0; p < 2; ++p) {
            int r = ar + p * 64;
            float4 v = *reinterpret_cast<const float4*>(&x[(size_t)(m0 + r) * I + k0 + ak]);
            As[ak + 0][r] = v.x;
            As[ak + 1][r] = v.y;
            As[ak + 2][r] = v.z;
            As[ak + 3][r] = v.w;
        }
        #pragma unroll
        for (int p = 0; p < 2; ++p) {
            int kk = bk + p * 8;
            float4 v = *reinterpret_cast<const float4*>(&w[(size_t)(k0 + kk) * H + j0 + bc]);
            *reinterpret_cast<float4*>(&Bs[kk][bc]) = v;
        }
        __syncthreads();

        #pragma unroll
        for (int kk = 0; kk < BK; ++kk) {
            double2 da = *reinterpret_cast<const double2*>(&As[kk][ty * 8]);
            double2 db = *reinterpret_cast<const double2*>(&As[kk][ty * 8 + 4]);
            ull arw[4] = {d2l(da.x), d2l(da.y), d2l(db.x), d2l(db.y)};
            float4 c0 = *reinterpret_cast<const float4*>(&Bs[kk][tx * 8]);
            float4 c1 = *reinterpret_cast<const float4*>(&Bs[kk][tx * 8 + 4]);
            float bf_[8] = {c0.x, c0.y, c0.z, c0.w, c1.x, c1.y, c1.z, c1.w};
            #pragma unroll
            for (int j = 0; j < 8; ++j) {
                ull bj = dup2(bf_[j]);
                #pragma unroll
                for (int i = 0; i < 4; ++i)
                    fma2(acc[i][j], arw[i], bj);
            }
        }
        __syncthreads();
    }

    // epilogue: unpack, add bias, scatter to [t][b][4H]
    #pragma unroll
    for (int i2 = 0; i2 < 4; ++i2) {
        #pragma unroll
        for (int half = 0; half < 2; ++half) {
            int m = m0 + ty * 8 + i2 * 2 + half;
            int t = m & (T - 1);
            int bi_ = m >> 9;
            size_t base = ((size_t)t * B + bi_) * G4H + n0;
            #pragma unroll
            for (int j = 0; j < 8; ++j) {
                float2 u = unpack2(acc[i2][j]);
                float v = half ? u.y : u.x;
                int n = tx * 8 + j;
                g_xproj[base + n] = v + bias[j0 + n];
            }
        }
    }
}

// ---------------------------------------------------------------------------
// Fused LSTM step, v2: f32x2 FMAs + double-buffered smem.
// Grid: 128 CTAs x 256 threads. CTA cg owns H-columns [cg*8, cg*8+8) for ALL
// 4 gates and all 64 batch rows. Tile: 64 rows x 32 fused cols, K=1024.
// Thread tile 4 rows x 2 cols held as 2x2 f32x2 accumulators.
// ---------------------------------------------------------------------------
static constexpr int KC = 32;            // K chunk
static constexpr int NCHUNK = H / KC;    // 32
static constexpr int HS_STRIDE = 68;     // 64 rows + pad
static constexpr int WS_STRIDE = 36;     // 32 fused cols + pad

__global__ void __launch_bounds__(256) lstm_step_kernel(
    int t,
    const float* __restrict__ wh0, const float* __restrict__ wh1,
    const float* __restrict__ wh2, const float* __restrict__ wh3,
    float* __restrict__ out)
{
    const int tid = threadIdx.x;
    const int cg = blockIdx.x;           // 0..127
    const int j0 = cg * 8;

    const float* __restrict__ hin = g_h[t & 1];
    float* __restrict__ hout = g_h[(t + 1) & 1];

    __shared__ float hs[2][KC * HS_STRIDE];
    __shared__ float ws[2][KC * WS_STRIDE];
    __shared__ float gt[64 * WS_STRIDE];

    const int tx = tid & 15;             // 16 col groups x 2 cols
    const int ty = tid >> 4;             // 16 row groups x 4 rows

    ull acc[2][2] = {{0ULL, 0ULL}, {0ULL, 0ULL}};  // [rowpair][col]

    // load mappings
    const int hr = tid >> 3;             // h row 0..31 (then +32)
    const int hkq = (tid & 7) * 4;       // k quad within chunk
    const int wkk = tid >> 3;            // ws k row 0..31
    const int wf4 = tid & 7;             // fused-col quad
    const int wgate = wf4 >> 1;
    const int wjj = (wf4 & 1) * 4;
    const float* __restrict__ wsel = (wgate == 0) ? wh0 : (wgate == 1) ? wh1
                                   : (wgate == 2) ? wh2 : wh3;

    // ---- prologue: load chunk 0 into buffer 0 ----
    {
        float4 h0 = *reinterpret_cast<const float4*>(&hin[hr * H + hkq]);
        float4 h1 = *reinterpret_cast<const float4*>(&hin[(hr + 32) * H + hkq]);
        float4 wv = *reinterpret_cast<const float4*>(&wsel[(size_t)wkk * H + j0 + wjj]);
        hs[0][(hkq + 0) * HS_STRIDE + hr] = h0.x;
        hs[0][(hkq + 1) * HS_STRIDE + hr] = h0.y;
        hs[0][(hkq + 2) * HS_STRIDE + hr] = h0.z;
        hs[0][(hkq + 3) * HS_STRIDE + hr] = h0.w;
        hs[0][(hkq + 0) * HS_STRIDE + hr + 32] = h1.x;
        hs[0][(hkq + 1) * HS_STRIDE + hr + 32] = h1.y;
        hs[0][(hkq + 2) * HS_STRIDE + hr + 32] = h1.z;
        hs[0][(hkq + 3) * HS_STRIDE + hr + 32] = h1.w;
        *reinterpret_cast<float4*>(&ws[0][wkk * WS_STRIDE + wf4 * 4]) = wv;
    }
    __syncthreads();

    for (int c = 0; c < NCHUNK; ++c) {
        const int cur = c & 1;

        // prefetch chunk c+1 into registers
        float4 nh0, nh1, nw;
        if (c + 1 < NCHUNK) {
            const int k0 = (c + 1) * KC;
            nh0 = *reinterpret_cast<const float4*>(&hin[hr * H + k0 + hkq]);
            nh1 = *reinterpret_cast<const float4*>(&hin[(hr + 32) * H + k0 + hkq]);
            nw  = *reinterpret_cast<const float4*>(&wsel[(size_t)(k0 + wkk) * H + j0 + wjj]);
        }

        // compute on current buffer
        #pragma unroll
        for (int kk = 0; kk < KC; ++kk) {
            double2 av = *reinterpret_cast<const double2*>(&hs[cur][kk * HS_STRIDE + ty * 4]);
            ull a01 = d2l(av.x);
            ull a23 = d2l(av.y);
            float2 bv = *reinterpret_cast<const float2*>(&ws[cur][kk * WS_STRIDE + tx * 2]);
            ull bx = dup2(bv.x);
            ull by = dup2(bv.y);
            fma2(acc[0][0], a01, bx);
            fma2(acc[1][0], a23, bx);
            fma2(acc[0][1], a01, by);
            fma2(acc[1][1], a23, by);
        }

        // store prefetched chunk to the other buffer
        if (c + 1 < NCHUNK) {
            const int nxt = cur ^ 1;
            hs[nxt][(hkq + 0) * HS_STRIDE + hr] = nh0.x;
            hs[nxt][(hkq + 1) * HS_STRIDE + hr] = nh0.y;
            hs[nxt][(hkq + 2) * HS_STRIDE + hr] = nh0.z;
            hs[nxt][(hkq + 3) * HS_STRIDE + hr] = nh0.w;
            hs[nxt][(hkq + 0) * HS_STRIDE + hr + 32] = nh1.x;
            hs[nxt][(hkq + 1) * HS_STRIDE + hr + 32] = nh1.y;
            hs[nxt][(hkq + 2) * HS_STRIDE + hr + 32] = nh1.z;
            hs[nxt][(hkq + 3) * HS_STRIDE + hr + 32] = nh1.w;
            *reinterpret_cast<float4*>(&ws[nxt][wkk * WS_STRIDE + wf4 * 4]) = nw;
        }
        __syncthreads();
    }

    // add xproj, stash gates in smem for the cross-gate pointwise
    {
        float accf[4][2];
        float2 u;
        u = unpack2(acc[0][0]); accf[0][0] = u.x; accf[1][0] = u.y;
        u = unpack2(acc[1][0]); accf[2][0] = u.x; accf[3][0] = u.y;
        u = unpack2(acc[0][1]); accf[0][1] = u.x; accf[1][1] = u.y;
        u = unpack2(acc[1][1]); accf[2][1] = u.x; accf[3][1] = u.y;

        #pragma unroll
        for (int r = 0; r < 4; ++r) {
            int row = ty * 4 + r;
            size_t xb = ((size_t)t * B + row) * G4H;
            #pragma unroll
            for (int cc = 0; cc < 2; ++cc) {
                int fc = tx * 2 + cc;
                int gate = fc >> 3;
                int jj = fc & 7;
                gt[row * WS_STRIDE + fc] = accf[r][cc] + g_xproj[xb + (size_t)gate * H + j0 + jj];
            }
        }
    }
    __syncthreads();

    // pointwise LSTM cell: 512 (row, j) elements, 2 per thread
    #pragma unroll
    for (int e0 = 0; e0 < 2; ++e0) {
        int e = tid * 2 + e0;
        int row = e >> 3;
        int jj = e & 7;
        float gi = gt[row * WS_STRIDE + 0 * 8 + jj];
        float gf = gt[row * WS_STRIDE + 1 * 8 + jj];
        float gg = gt[row * WS_STRIDE + 2 * 8 + jj];
        float go = gt[row * WS_STRIDE + 3 * 8 + jj];
        float ig = fast_sigmoid(gi);
        float fg = fast_sigmoid(gf);
        float gv = fast_tanh(gg);
        float og = fast_sigmoid(go);
        int j = j0 + jj;
        float c = fg * g_c[row * H + j] + ig * gv;
        g_c[row * H + j] = c;
        float h = og * fast_tanh(c);
        hout[row * H + j] = h;
        out[((size_t)row * T + t) * H + j] = h;
        if (t == T - 1) {
            size_t off = (size_t)B * T * H;
            out[off + (size_t)row * H + j] = h;                   // ht
            out[off + (size_t)B * H + (size_t)row * H + j] = c;   // ct
        }
    }
}

// ---------------------------------------------------------------------------
extern "C" void kernel_launch(void* const* d_in, const int* in_sizes, int n_in,
                              void* d_out, int out_size)
{
    const float* x   = (const float*)d_in[0];
    const float* wii = (const float*)d_in[1];
    const float* whi = (const float*)d_in[2];
    const float* bi  = (const float*)d_in[3];
    const float* wif = (const float*)d_in[4];
    const float* whf = (const float*)d_in[5];
    const float* bf  = (const float*)d_in[6];
    const float* wig = (const float*)d_in[7];
    const float* whg = (const float*)d_in[8];
    const float* bg  = (const float*)d_in[9];
    const float* wio = (const float*)d_in[10];
    const float* who = (const float*)d_in[11];
    const float* bo  = (const float*)d_in[12];
    float* out = (float*)d_out;

    init_kernel<<<(B * H + 255) / 256, 256>>>();

    dim3 gx(G4H / BN, (B * T) / BM);   // (32, 256)
    xproj_kernel<<<gx, 256>>>(x, wii, wif, wig, wio, bi, bf, bg, bo);

    for (int t = 0; t < T; ++t)
        lstm_step_kernel<<<128, 256>>>(t, whi, whf, whg, who, out);
}

// round 4
// speedup vs baseline: 1.4047x; 1.3128x over previous
#include <cuda_runtime.h>
#include <math.h>

typedef unsigned long long ull;

// Problem constants
static constexpr int B = 64;
static constexpr int T = 512;
static constexpr int I = 1024;
static constexpr int H = 1024;
static constexpr int G4H = 4 * H;   // 4096

static constexpr int NCTA = 128;
static constexpr int NTHR = 512;

// Scratch in device globals (no allocation allowed)
__device__ float g_xproj[(size_t)T * B * G4H];  // [T][B][4H]
__device__ float g_h[2][B * H];                 // h ping-pong
__device__ unsigned g_bar_count = 0;
__device__ unsigned g_bar_sense = 0;

// ---------------------------------------------------------------------------
// f32x2 packed-FMA helpers
// ---------------------------------------------------------------------------
__device__ __forceinline__ ull dup2(float x) {
    ull r; asm("mov.b64 %0, {%1, %1};" : "=l"(r) : "f"(x)); return r;
}
__device__ __forceinline__ void fma2(ull& d, ull a, ull b) {
    asm("fma.rn.f32x2 %0, %1, %2, %0;" : "+l"(d) : "l"(a), "l"(b));
}
__device__ __forceinline__ float2 unpack2(ull v) {
    float2 f; asm("mov.b64 {%0, %1}, %2;" : "=f"(f.x), "=f"(f.y) : "l"(v)); return f;
}
__device__ __forceinline__ ull d2l(double d) { return __double_as_longlong(d); }

__device__ __forceinline__ float fast_tanh(float x) {
    float y; asm("tanh.approx.f32 %0, %1;" : "=f"(y) : "f"(x)); return y;
}
__device__ __forceinline__ float fast_sigmoid(float x) {
    return 0.5f * fast_tanh(0.5f * x) + 0.5f;
}

// ---------------------------------------------------------------------------
// init: zero h[0]
// ---------------------------------------------------------------------------
__global__ void init_kernel() {
    int i = blockIdx.x * blockDim.x + threadIdx.x;
    if (i < B * H) g_h[0][i] = 0.0f;
}

// ---------------------------------------------------------------------------
// xproj GEMM (unchanged from R3): C = x @ Wx + b, scattered to [t][b][4H]
// ---------------------------------------------------------------------------
static constexpr int BM = 128;
static constexpr int BN = 128;
static constexpr int BK = 16;

__global__ void __launch_bounds__(256) xproj_kernel(
    const float* __restrict__ x,
    const float* __restrict__ w0, const float* __restrict__ w1,
    const float* __restrict__ w2, const float* __restrict__ w3,
    const float* __restrict__ b0, const float* __restrict__ b1,
    const float* __restrict__ b2, const float* __restrict__ b3)
{
    const int tid = threadIdx.x;
    const int m0 = blockIdx.y * BM;
    const int n0 = blockIdx.x * BN;
    const int gate = n0 >> 10;
    const float* __restrict__ w = (gate == 0) ? w0 : (gate == 1) ? w1 : (gate == 2) ? w2 : w3;
    const float* __restrict__ bias = (gate == 0) ? b0 : (gate == 1) ? b1 : (gate == 2) ? b2 : b3;
    const int j0 = n0 & (H - 1);

    __shared__ float As[BK][BM + 4];
    __shared__ float Bs[BK][BN + 4];

    const int tx = tid & 15;
    const int ty = tid >> 4;

    ull acc[4][8];
    #pragma unroll
    for (int i = 0; i < 4; ++i)
        #pragma unroll
        for (int j = 0; j < 8; ++j) acc[i][j] = 0ULL;

    const int ar = tid >> 2;
    const int ak = (tid & 3) * 4;
    const int bk = tid >> 5;
    const int bc = (tid & 31) * 4;

    for (int k0 = 0; k0 < I; k0 += BK) {
        #pragma unroll
        for (int p = 0; p < 2; ++p) {
            int r = ar + p * 64;
            float4 v = *reinterpret_cast<const float4*>(&x[(size_t)(m0 + r) * I + k0 + ak]);
            As[ak + 0][r] = v.x;
            As[ak + 1][r] = v.y;
            As[ak + 2][r] = v.z;
            As[ak + 3][r] = v.w;
        }
        #pragma unroll
        for (int p = 0; p < 2; ++p) {
            int kk = bk + p * 8;
            float4 v = *reinterpret_cast<const float4*>(&w[(size_t)(k0 + kk) * H + j0 + bc]);
            *reinterpret_cast<float4*>(&Bs[kk][bc]) = v;
        }
        __syncthreads();

        #pragma unroll
        for (int kk = 0; kk < BK; ++kk) {
            double2 da = *reinterpret_cast<const double2*>(&As[kk][ty * 8]);
            double2 db = *reinterpret_cast<const double2*>(&As[kk][ty * 8 + 4]);
            ull arw[4] = {d2l(da.x), d2l(da.y), d2l(db.x), d2l(db.y)};
            float4 c0 = *reinterpret_cast<const float4*>(&Bs[kk][tx * 8]);
            float4 c1 = *reinterpret_cast<const float4*>(&Bs[kk][tx * 8 + 4]);
            float bf_[8] = {c0.x, c0.y, c0.z, c0.w, c1.x, c1.y, c1.z, c1.w};
            #pragma unroll
            for (int j = 0; j < 8; ++j) {
                ull bj = dup2(bf_[j]);
                #pragma unroll
                for (int i = 0; i < 4; ++i)
                    fma2(acc[i][j], arw[i], bj);
            }
        }
        __syncthreads();
    }

    #pragma unroll
    for (int i2 = 0; i2 < 4; ++i2) {
        #pragma unroll
        for (int half = 0; half < 2; ++half) {
            int m = m0 + ty * 8 + i2 * 2 + half;
            int t = m & (T - 1);
            int bi_ = m >> 9;
            size_t base = ((size_t)t * B + bi_) * G4H + n0;
            #pragma unroll
            for (int j = 0; j < 8; ++j) {
                float2 u = unpack2(acc[i2][j]);
                float v = half ? u.y : u.x;
                int n = tx * 8 + j;
                g_xproj[base + n] = v + bias[j0 + n];
            }
        }
    }
}

// ---------------------------------------------------------------------------
// Persistent LSTM recurrence.
// 128 CTAs x 512 threads, 1 CTA/SM (smem-bound). CTA cg owns H-cols
// [cg*8, cg*8+8) x 4 gates = 32 fused cols, all 64 batch rows, all T steps.
//
// - Wh slice [1024 K][32 fc] lives in SMEM for the whole kernel (128 KB).
// - K split across warpgroups: half 0 (warps 0-7) K[0:512], half 1 K[512:1024].
// - h read via __ldcg (L1 would go stale across ping-pong), staged per-chunk
//   in double-buffered smem, transposed [k][row].
// - c lives in a register per thread for all 512 steps.
// - Sense-reversal grid barrier between steps.
// ---------------------------------------------------------------------------
static constexpr int KC = 32;
static constexpr int KHALF = H / 2;          // 512
static constexpr int NCHUNK = KHALF / KC;    // 16
static constexpr int HS_STRIDE = 68;         // 64 rows + pad (16B-aligned rows)
static constexpr int GT_STRIDE = 36;

static constexpr int WS_FLOATS = H * 32;                     // 32768
static constexpr int HS_FLOATS = 2 * 2 * KC * HS_STRIDE;     // 8704
static constexpr int GT_FLOATS = 64 * GT_STRIDE;             // 2304
static constexpr size_t SMEM_BYTES = (WS_FLOATS + HS_FLOATS + GT_FLOATS) * sizeof(float); // 209920

__device__ __forceinline__ void grid_barrier(unsigned* s_sense_ptr) {
    __threadfence();
    __syncthreads();
    if (threadIdx.x == 0) {
        unsigned s = *s_sense_ptr ^ 1u;
        *s_sense_ptr = s;
        if (atomicAdd(&g_bar_count, 1u) == NCTA - 1u) {
            g_bar_count = 0;
            asm volatile("st.release.gpu.global.u32 [%0], %1;"
                         :: "l"(&g_bar_sense), "r"(s) : "memory");
        } else {
            unsigned v;
            while (true) {
                asm volatile("ld.acquire.gpu.global.u32 %0, [%1];"
                             : "=r"(v) : "l"(&g_bar_sense) : "memory");
                if (v == s) break;
                __nanosleep(32);
            }
        }
    }
    __syncthreads();
}

__global__ void __launch_bounds__(NTHR, 1) lstm_persistent(
    const float* __restrict__ wh0, const float* __restrict__ wh1,
    const float* __restrict__ wh2, const float* __restrict__ wh3,
    float* __restrict__ out)
{
    extern __shared__ float smem[];
    float* ws = smem;                        // [1024][32]
    float* hs = smem + WS_FLOATS;            // [half][buf][KC][HS_STRIDE]
    float* gt = smem + WS_FLOATS + HS_FLOATS;
    __shared__ unsigned s_sense;

    const int tid = threadIdx.x;
    const int cg = blockIdx.x;
    const int j0 = cg * 8;
    const int half = tid >> 8;
    const int t256 = tid & 255;
    const int tx = t256 & 15;                // 2 fused cols
    const int ty = t256 >> 4;                // 4 rows
    const int khbase = half * KHALF;
    float* hsl = hs + half * (2 * KC * HS_STRIDE);

    // ---- load Wh slice into smem once ----
    for (int idx = tid; idx < 8192; idx += NTHR) {
        int k = idx >> 3;
        int g4 = idx & 7;
        int gate = g4 >> 1;
        int jj4 = (g4 & 1) * 4;
        const float* __restrict__ wsel = (gate == 0) ? wh0 : (gate == 1) ? wh1
                                       : (gate == 2) ? wh2 : wh3;
        float4 v = *reinterpret_cast<const float4*>(&wsel[(size_t)k * H + j0 + jj4]);
        *reinterpret_cast<float4*>(&ws[k * 32 + gate * 8 + jj4]) = v;
    }
    if (tid == 0) s_sense = 0;
    __syncthreads();

    // cell-state registers: thread owns (prow, pjj)
    const int prow = tid >> 3;               // 0..63
    const int pjj = tid & 7;
    float creg = 0.0f;

    // h loader mapping (per half)
    const int hr = t256 >> 3;                // 0..31 (then +32)
    const int hkq = (t256 & 7) * 4;

    const int gate_c = (tx * 2) >> 3;        // gate of this thread's col pair
    const int jj_c = (tx * 2) & 7;

    for (int t = 0; t < T; ++t) {
        const float* __restrict__ hin = g_h[t & 1];
        float* __restrict__ hout = g_h[(t + 1) & 1];

        // prefetch xproj for this thread's tile (half 0 only)
        float2 xp[4];
        if (half == 0) {
            size_t base = (size_t)t * B * G4H + (size_t)gate_c * H + j0 + jj_c;
            #pragma unroll
            for (int r = 0; r < 4; ++r)
                xp[r] = *reinterpret_cast<const float2*>(&g_xproj[base + (size_t)(ty * 4 + r) * G4H]);
        }

        // prologue: stage chunk 0
        {
            float4 h0 = __ldcg(reinterpret_cast<const float4*>(&hin[hr * H + khbase + hkq]));
            float4 h1 = __ldcg(reinterpret_cast<const float4*>(&hin[(hr + 32) * H + khbase + hkq]));
            float* b0 = hsl;
            b0[(hkq + 0) * HS_STRIDE + hr] = h0.x;
            b0[(hkq + 1) * HS_STRIDE + hr] = h0.y;
            b0[(hkq + 2) * HS_STRIDE + hr] = h0.z;
            b0[(hkq + 3) * HS_STRIDE + hr] = h0.w;
            b0[(hkq + 0) * HS_STRIDE + hr + 32] = h1.x;
            b0[(hkq + 1) * HS_STRIDE + hr + 32] = h1.y;
            b0[(hkq + 2) * HS_STRIDE + hr + 32] = h1.z;
            b0[(hkq + 3) * HS_STRIDE + hr + 32] = h1.w;
        }
        __syncthreads();

        ull acc00 = 0, acc01 = 0, acc10 = 0, acc11 = 0;

        for (int c = 0; c < NCHUNK; ++c) {
            const float* hb = hsl + (c & 1) * KC * HS_STRIDE;

            float4 nh0, nh1;
            if (c + 1 < NCHUNK) {
                int k0 = khbase + (c + 1) * KC;
                nh0 = __ldcg(reinterpret_cast<const float4*>(&hin[hr * H + k0 + hkq]));
                nh1 = __ldcg(reinterpret_cast<const float4*>(&hin[(hr + 32) * H + k0 + hkq]));
            }

            const float* wrow = ws + (size_t)(khbase + c * KC) * 32;
            #pragma unroll
            for (int kk = 0; kk < KC; ++kk) {
                double2 av = *reinterpret_cast<const double2*>(&hb[kk * HS_STRIDE + ty * 4]);
                float2 bv = *reinterpret_cast<const float2*>(&wrow[kk * 32 + tx * 2]);
                ull a01 = d2l(av.x);
                ull a23 = d2l(av.y);
                ull bx = dup2(bv.x);
                ull by = dup2(bv.y);
                fma2(acc00, a01, bx);
                fma2(acc10, a23, bx);
                fma2(acc01, a01, by);
                fma2(acc11, a23, by);
            }

            if (c + 1 < NCHUNK) {
                float* bn = hsl + ((c + 1) & 1) * KC * HS_STRIDE;
                bn[(hkq + 0) * HS_STRIDE + hr] = nh0.x;
                bn[(hkq + 1) * HS_STRIDE + hr] = nh0.y;
                bn[(hkq + 2) * HS_STRIDE + hr] = nh0.z;
                bn[(hkq + 3) * HS_STRIDE + hr] = nh0.w;
                bn[(hkq + 0) * HS_STRIDE + hr + 32] = nh1.x;
                bn[(hkq + 1) * HS_STRIDE + hr + 32] = nh1.y;
                bn[(hkq + 2) * HS_STRIDE + hr + 32] = nh1.z;
                bn[(hkq + 3) * HS_STRIDE + hr + 32] = nh1.w;
            }
            __syncthreads();
        }

        // combine halves in gt
        float accf[4][2];
        {
            float2 u;
            u = unpack2(acc00); accf[0][0] = u.x; accf[1][0] = u.y;
            u = unpack2(acc10); accf[2][0] = u.x; accf[3][0] = u.y;
            u = unpack2(acc01); accf[0][1] = u.x; accf[1][1] = u.y;
            u = unpack2(acc11); accf[2][1] = u.x; accf[3][1] = u.y;
        }
        if (half == 0) {
            #pragma unroll
            for (int r = 0; r < 4; ++r) {
                int row = ty * 4 + r;
                gt[row * GT_STRIDE + tx * 2 + 0] = accf[r][0] + xp[r].x;
                gt[row * GT_STRIDE + tx * 2 + 1] = accf[r][1] + xp[r].y;
            }
        }
        __syncthreads();
        if (half == 1) {
            #pragma unroll
            for (int r = 0; r < 4; ++r) {
                int row = ty * 4 + r;
                gt[row * GT_STRIDE + tx * 2 + 0] += accf[r][0];
                gt[row * GT_STRIDE + tx * 2 + 1] += accf[r][1];
            }
        }
        __syncthreads();

        // pointwise LSTM cell: one element per thread
        {
            float gi = gt[prow * GT_STRIDE + 0 * 8 + pjj];
            float gf = gt[prow * GT_STRIDE + 1 * 8 + pjj];
            float gg = gt[prow * GT_STRIDE + 2 * 8 + pjj];
            float go = gt[prow * GT_STRIDE + 3 * 8 + pjj];
            float ig = fast_sigmoid(gi);
            float fg = fast_sigmoid(gf);
            float gv = fast_tanh(gg);
            float og = fast_sigmoid(go);
            creg = fg * creg + ig * gv;
            float hv = og * fast_tanh(creg);
            int j = j0 + pjj;
            hout[prow * H + j] = hv;
            out[((size_t)prow * T + t) * H + j] = hv;
            if (t == T - 1) {
                size_t off = (size_t)B * T * H;
                out[off + (size_t)prow * H + j] = hv;
                out[off + (size_t)B * H + (size_t)prow * H + j] = creg;
            }
        }

        grid_barrier(&s_sense);
    }
}

// ---------------------------------------------------------------------------
extern "C" void kernel_launch(void* const* d_in, const int* in_sizes, int n_in,
                              void* d_out, int out_size)
{
    const float* x   = (const float*)d_in[0];
    const float* wii = (const float*)d_in[1];
    const float* whi = (const float*)d_in[2];
    const float* bi  = (const float*)d_in[3];
    const float* wif = (const float*)d_in[4];
    const float* whf = (const float*)d_in[5];
    const float* bf  = (const float*)d_in[6];
    const float* wig = (const float*)d_in[7];
    const float* whg = (const float*)d_in[8];
    const float* bg  = (const float*)d_in[9];
    const float* wio = (const float*)d_in[10];
    const float* who = (const float*)d_in[11];
    const float* bo  = (const float*)d_in[12];
    float* out = (float*)d_out;

    cudaFuncSetAttribute(lstm_persistent,
                         cudaFuncAttributeMaxDynamicSharedMemorySize,
                         (int)SMEM_BYTES);

    init_kernel<<<(B * H + 255) / 256, 256>>>();

    dim3 gx(G4H / BN, (B * T) / BM);   // (32, 256)
    xproj_kernel<<<gx, 256>>>(x, wii, wif, wig, wio, bi, bf, bg, bo);

    lstm_persistent<<<NCTA, NTHR, SMEM_BYTES>>>(whi, whf, whg, who, out);
}